// round 1
// baseline (speedup 1.0000x reference)
#include <cuda_runtime.h>
#include <cuda_bf16.h>

#define B_  16
#define T_  64
#define V_  32000
#define E_  256
#define H_  1024
#define G4  4096
#define EH  1280   // E + H   (encoder lstm input)
#define DH  2304   // E + H + H (decoder lstm input: [emb, attn, h])
#define KS_ENC 10  // 1280 / 10 = 128
#define KS_DEC 12  // 2304 / 12 = 192
#define KS_Q   4   // 1024 / 4  = 256
#define KS_A   8   // 2048 / 8  = 256
#define NEGV (-1e9f)

// ---------------- device scratch (no allocations allowed) ----------------
__device__ float g_qemb[B_*T_*E_];
__device__ float g_remb[B_*T_*E_];
__device__ float g_h[B_*H_];
__device__ float g_c[B_*H_];
__device__ float g_attn[B_*H_];
__device__ float g_ctx[B_*H_];
__device__ float g_mem[B_*T_*H_];
__device__ float g_keys[B_*T_*H_];
__device__ float g_dec_out[B_*T_*H_];
__device__ float g_zpart[KS_DEC*B_*G4];   // shared by enc (10 splits) & dec (12)
__device__ float g_qpart[KS_Q*B_*H_];
__device__ float g_apart[KS_A*B_*H_];
__device__ float g_scores[B_*T_];

// ---------------- math helpers (fast but ~1e-6 accurate) -----------------
__device__ __forceinline__ float sigf(float x) {
    return 1.0f / (1.0f + __expf(-x));          // saturates cleanly at +-inf
}
__device__ __forceinline__ float tanh_fast(float x) {
    float ax = fabsf(x);
    float e  = __expf(2.0f * ax);               // inf for large ax -> r = 1
    float r  = 1.0f - 2.0f / (e + 1.0f);
    return copysignf(r, x);
}

// ---------------- K0: embedding gather + zero state ----------------------
// grid 2240 x 256 covers 2*B*T*E embed elements + 3*B*H zeros exactly
__global__ void k_init(const int* __restrict__ enc_in,
                       const int* __restrict__ dec_in,
                       const float* __restrict__ emb) {
    int i = blockIdx.x * 256 + threadIdx.x;
    const int NE = B_*T_*E_;           // 262144
    if (i < NE) {
        int bt = i >> 8, e = i & 255;
        g_qemb[i] = emb[(size_t)enc_in[bt] * E_ + e];
    } else if (i < 2*NE) {
        int j = i - NE;
        int bt = j >> 8, e = j & 255;
        g_remb[j] = emb[(size_t)dec_in[bt] * E_ + e];
    } else {
        int j = i - 2*NE;
        if (j < B_*H_)            g_h[j] = 0.f;
        else if (j < 2*B_*H_)     g_c[j - B_*H_] = 0.f;
        else if (j < 3*B_*H_)     g_attn[j - 2*B_*H_] = 0.f;
    }
}

// ---------------- encoder GEMM (split-K partials) -------------------------
// grid (16 colblocks, KS_ENC), 256 threads; each thread: 1 col x 16 batches
__global__ __launch_bounds__(256) void k_enc_gemm(const float* __restrict__ W, int t) {
    __shared__ __align__(16) float xs[128*16];  // xs[k*16 + b]
    const int k0  = blockIdx.y * 128;
    const int col = blockIdx.x * 256 + threadIdx.x;
    for (int i = threadIdx.x; i < 128*16; i += 256) {
        int k = i >> 4, b = i & 15;
        int gk = k0 + k;
        xs[i] = (gk < E_) ? g_qemb[(b*T_ + t)*E_ + gk]
                          : g_h[b*H_ + (gk - E_)];
    }
    __syncthreads();
    float acc[16];
#pragma unroll
    for (int b = 0; b < 16; b++) acc[b] = 0.f;
    const float* Wp = W + (size_t)k0 * G4 + col;
#pragma unroll 4
    for (int k = 0; k < 128; k++) {
        float w = Wp[(size_t)k * G4];
        const float4* xr = (const float4*)(xs + k*16);
        float4 x0 = xr[0], x1 = xr[1], x2 = xr[2], x3 = xr[3];
        acc[0]+=x0.x*w; acc[1]+=x0.y*w; acc[2]+=x0.z*w; acc[3]+=x0.w*w;
        acc[4]+=x1.x*w; acc[5]+=x1.y*w; acc[6]+=x1.z*w; acc[7]+=x1.w*w;
        acc[8]+=x2.x*w; acc[9]+=x2.y*w; acc[10]+=x2.z*w; acc[11]+=x2.w*w;
        acc[12]+=x3.x*w; acc[13]+=x3.y*w; acc[14]+=x3.z*w; acc[15]+=x3.w*w;
    }
    float* zp = g_zpart + (size_t)(blockIdx.y*16) * G4 + col;
#pragma unroll
    for (int b = 0; b < 16; b++) zp[(size_t)b * G4] = acc[b];
}

// ---------------- encoder gates: reduce partials, LSTM update -------------
__global__ void k_enc_gates(const float* __restrict__ bias,
                            const int* __restrict__ enc_len, int t) {
    int g = blockIdx.x * 256 + threadIdx.x;     // 0 .. 16383
    int b = g >> 10, hh = g & 1023;
    float zi = bias[hh], zj = bias[H_+hh], zf = bias[2*H_+hh], zo = bias[3*H_+hh];
#pragma unroll
    for (int s = 0; s < KS_ENC; s++) {
        const float* zp = g_zpart + (size_t)(s*16 + b) * G4;
        zi += zp[hh]; zj += zp[H_+hh]; zf += zp[2*H_+hh]; zo += zp[3*H_+hh];
    }
    float c  = g_c[g];
    float cn = c * sigf(zf + 1.0f) + sigf(zi) * tanh_fast(zj);
    float hn = tanh_fast(cn) * sigf(zo);
    bool valid = t < enc_len[b];
    if (valid) { g_c[g] = cn; g_h[g] = hn; }
    g_mem[(size_t)(b*T_ + t) * H_ + hh] = valid ? hn : 0.f;
}

// ---------------- decoder GEMM (x = [emb, attn, h]) -----------------------
__global__ __launch_bounds__(256) void k_dec_gemm(const float* __restrict__ W, int t) {
    __shared__ __align__(16) float xs[192*16];
    const int k0  = blockIdx.y * 192;
    const int col = blockIdx.x * 256 + threadIdx.x;
    for (int i = threadIdx.x; i < 192*16; i += 256) {
        int k = i >> 4, b = i & 15;
        int gk = k0 + k;
        float v;
        if (gk < E_)        v = g_remb[(b*T_ + t)*E_ + gk];
        else if (gk < EH)   v = g_attn[b*H_ + (gk - E_)];
        else                v = g_h[b*H_ + (gk - EH)];
        xs[i] = v;
    }
    __syncthreads();
    float acc[16];
#pragma unroll
    for (int b = 0; b < 16; b++) acc[b] = 0.f;
    const float* Wp = W + (size_t)k0 * G4 + col;
#pragma unroll 4
    for (int k = 0; k < 192; k++) {
        float w = Wp[(size_t)k * G4];
        const float4* xr = (const float4*)(xs + k*16);
        float4 x0 = xr[0], x1 = xr[1], x2 = xr[2], x3 = xr[3];
        acc[0]+=x0.x*w; acc[1]+=x0.y*w; acc[2]+=x0.z*w; acc[3]+=x0.w*w;
        acc[4]+=x1.x*w; acc[5]+=x1.y*w; acc[6]+=x1.z*w; acc[7]+=x1.w*w;
        acc[8]+=x2.x*w; acc[9]+=x2.y*w; acc[10]+=x2.z*w; acc[11]+=x2.w*w;
        acc[12]+=x3.x*w; acc[13]+=x3.y*w; acc[14]+=x3.z*w; acc[15]+=x3.w*w;
    }
    float* zp = g_zpart + (size_t)(blockIdx.y*16) * G4 + col;
#pragma unroll
    for (int b = 0; b < 16; b++) zp[(size_t)b * G4] = acc[b];
}

// ---------------- decoder gates (unconditional carry update) --------------
__global__ void k_dec_gates(const float* __restrict__ bias) {
    int g = blockIdx.x * 256 + threadIdx.x;
    int b = g >> 10, hh = g & 1023;
    float zi = bias[hh], zj = bias[H_+hh], zf = bias[2*H_+hh], zo = bias[3*H_+hh];
#pragma unroll
    for (int s = 0; s < KS_DEC; s++) {
        const float* zp = g_zpart + (size_t)(s*16 + b) * G4;
        zi += zp[hh]; zj += zp[H_+hh]; zf += zp[2*H_+hh]; zo += zp[3*H_+hh];
    }
    float c  = g_c[g];
    float cn = c * sigf(zf + 1.0f) + sigf(zi) * tanh_fast(zj);
    float hn = tanh_fast(cn) * sigf(zo);
    g_c[g] = cn; g_h[g] = hn;   // h2, c2
}

// ---------------- query = h2 @ Wq (split-K partials) ----------------------
// grid (8 colblocks of 128, KS_Q), 128 threads
__global__ __launch_bounds__(128) void k_query(const float* __restrict__ Wq) {
    __shared__ __align__(16) float xs[256*16];
    const int k0  = blockIdx.y * 256;
    const int col = blockIdx.x * 128 + threadIdx.x;
    for (int i = threadIdx.x; i < 256*16; i += 128) {
        int k = i >> 4, b = i & 15;
        xs[i] = g_h[b*H_ + k0 + k];
    }
    __syncthreads();
    float acc[16];
#pragma unroll
    for (int b = 0; b < 16; b++) acc[b] = 0.f;
    const float* Wp = Wq + (size_t)k0 * H_ + col;
#pragma unroll 4
    for (int k = 0; k < 256; k++) {
        float w = Wp[(size_t)k * H_];
        const float4* xr = (const float4*)(xs + k*16);
        float4 x0 = xr[0], x1 = xr[1], x2 = xr[2], x3 = xr[3];
        acc[0]+=x0.x*w; acc[1]+=x0.y*w; acc[2]+=x0.z*w; acc[3]+=x0.w*w;
        acc[4]+=x1.x*w; acc[5]+=x1.y*w; acc[6]+=x1.z*w; acc[7]+=x1.w*w;
        acc[8]+=x2.x*w; acc[9]+=x2.y*w; acc[10]+=x2.z*w; acc[11]+=x2.w*w;
        acc[12]+=x3.x*w; acc[13]+=x3.y*w; acc[14]+=x3.z*w; acc[15]+=x3.w*w;
    }
    float* qp = g_qpart + (size_t)(blockIdx.y*16) * H_ + col;
#pragma unroll
    for (int b = 0; b < 16; b++) qp[(size_t)b * H_] = acc[b];
}

// ---------------- scores[b][t2] = v . tanh(keys + query) ------------------
// grid (t2=64, b=16), 128 threads
__global__ __launch_bounds__(128) void k_scores(const float* __restrict__ v_att) {
    const int t2 = blockIdx.x, b = blockIdx.y;
    const int tid = threadIdx.x;
    const float* kr = g_keys + (size_t)(b*T_ + t2) * H_;
    float partial = 0.f;
    for (int h = tid; h < H_; h += 128) {
        float q = g_qpart[(0*16+b)*H_ + h] + g_qpart[(1*16+b)*H_ + h]
                + g_qpart[(2*16+b)*H_ + h] + g_qpart[(3*16+b)*H_ + h];
        partial += tanh_fast(kr[h] + q) * v_att[h];
    }
    __shared__ float red[128];
    red[tid] = partial; __syncthreads();
#pragma unroll
    for (int s = 64; s > 0; s >>= 1) {
        if (tid < s) red[tid] += red[tid + s];
        __syncthreads();
    }
    if (tid == 0) g_scores[b*T_ + t2] = red[0];
}

// ---------------- softmax (per-block redundant) + context -----------------
// grid (8 hchunks, 16 b), 128 threads
__global__ __launch_bounds__(128) void k_ctx(const int* __restrict__ enc_len) {
    const int b = blockIdx.y;
    const int tid = threadIdx.x;
    __shared__ float al[64];
    if (tid < 32) {
        int L = enc_len[b];
        float s0 = (tid      < L) ? g_scores[b*T_ + tid]      : NEGV;
        float s1 = (tid + 32 < L) ? g_scores[b*T_ + tid + 32] : NEGV;
        float m = fmaxf(s0, s1);
#pragma unroll
        for (int o = 16; o > 0; o >>= 1) m = fmaxf(m, __shfl_xor_sync(0xffffffffu, m, o));
        float e0 = __expf(s0 - m), e1 = __expf(s1 - m);
        float s = e0 + e1;
#pragma unroll
        for (int o = 16; o > 0; o >>= 1) s += __shfl_xor_sync(0xffffffffu, s, o);
        float inv = 1.f / s;
        al[tid] = e0 * inv; al[tid + 32] = e1 * inv;
    }
    __syncthreads();
    int h = blockIdx.x * 128 + tid;
    const float* mb = g_mem + (size_t)b * T_ * H_ + h;
    float acc = 0.f;
#pragma unroll
    for (int t2 = 0; t2 < T_; t2++) acc += al[t2] * mb[(size_t)t2 * H_];
    g_ctx[b*H_ + h] = acc;
}

// ---------------- attn2 = [h2, context] @ attn_kernel ---------------------
// grid (8 colblocks, KS_A), 128 threads
__global__ __launch_bounds__(128) void k_attn2(const float* __restrict__ Wa) {
    __shared__ __align__(16) float xs[256*16];
    const int k0  = blockIdx.y * 256;
    const int col = blockIdx.x * 128 + threadIdx.x;
    for (int i = threadIdx.x; i < 256*16; i += 128) {
        int k = i >> 4, b = i & 15;
        int gk = k0 + k;
        xs[i] = (gk < H_) ? g_h[b*H_ + gk] : g_ctx[b*H_ + (gk - H_)];
    }
    __syncthreads();
    float acc[16];
#pragma unroll
    for (int b = 0; b < 16; b++) acc[b] = 0.f;
    const float* Wp = Wa + (size_t)k0 * H_ + col;
#pragma unroll 4
    for (int k = 0; k < 256; k++) {
        float w = Wp[(size_t)k * H_];
        const float4* xr = (const float4*)(xs + k*16);
        float4 x0 = xr[0], x1 = xr[1], x2 = xr[2], x3 = xr[3];
        acc[0]+=x0.x*w; acc[1]+=x0.y*w; acc[2]+=x0.z*w; acc[3]+=x0.w*w;
        acc[4]+=x1.x*w; acc[5]+=x1.y*w; acc[6]+=x1.z*w; acc[7]+=x1.w*w;
        acc[8]+=x2.x*w; acc[9]+=x2.y*w; acc[10]+=x2.z*w; acc[11]+=x2.w*w;
        acc[12]+=x3.x*w; acc[13]+=x3.y*w; acc[14]+=x3.z*w; acc[15]+=x3.w*w;
    }
    float* ap = g_apart + (size_t)(blockIdx.y*16) * H_ + col;
#pragma unroll
    for (int b = 0; b < 16; b++) ap[(size_t)b * H_] = acc[b];
}

// ---------------- attn finish: carry + masked dec_out ---------------------
__global__ void k_attn_fin(const int* __restrict__ dec_len, int t) {
    int g = blockIdx.x * 256 + threadIdx.x;
    int b = g >> 10, hh = g & 1023;
    float a = 0.f;
#pragma unroll
    for (int s = 0; s < KS_A; s++) a += g_apart[(size_t)(s*16 + b) * H_ + hh];
    g_attn[g] = a;                                   // carry (unmasked)
    g_dec_out[(size_t)(b*T_ + t) * H_ + hh] = (t < dec_len[b]) ? a : 0.f;
}

// ---------------- big SGEMM: 128x128 tile, BK=8, 8x8 microtile ------------
// mode 0: keys = g_mem @ Bm      (N = 1024, C = g_keys)
// mode 1: out  = g_dec_out @ Bm  (N = 32000, C = Cext)
__global__ __launch_bounds__(256, 2) void sgemm128(int mode,
                                                   const float* __restrict__ Bm,
                                                   float* __restrict__ Cext,
                                                   int N) {
    const float* A = mode ? g_dec_out : g_mem;
    float* C = mode ? Cext : g_keys;
    __shared__ __align__(16) float As[2][8][132];
    __shared__ __align__(16) float Bs[2][8][128];
    const int tid = threadIdx.x;
    const int m0 = blockIdx.y * 128, n0 = blockIdx.x * 128;
    const int tx = tid & 15, ty = tid >> 4;
    const int la_r = tid >> 1, la_c = (tid & 1) * 4;
    const int lb_r = tid >> 5, lb_c = (tid & 31) * 4;

    float acc[8][8];
#pragma unroll
    for (int i = 0; i < 8; i++)
#pragma unroll
        for (int j = 0; j < 8; j++) acc[i][j] = 0.f;

    {   // preload tile 0
        float4 a4 = *(const float4*)(A  + (size_t)(m0 + la_r) * 1024 + la_c);
        float4 b4 = *(const float4*)(Bm + (size_t)lb_r * N + n0 + lb_c);
        As[0][la_c+0][la_r] = a4.x; As[0][la_c+1][la_r] = a4.y;
        As[0][la_c+2][la_r] = a4.z; As[0][la_c+3][la_r] = a4.w;
        *(float4*)&Bs[0][lb_r][lb_c] = b4;
    }
    __syncthreads();

    const int nk = 1024 / 8;
    for (int kt = 0; kt < nk; kt++) {
        const int cur = kt & 1;
        float4 a4n, b4n;
        const bool nx = (kt + 1) < nk;
        if (nx) {
            int kb = (kt + 1) * 8;
            a4n = *(const float4*)(A  + (size_t)(m0 + la_r) * 1024 + kb + la_c);
            b4n = *(const float4*)(Bm + (size_t)(kb + lb_r) * N + n0 + lb_c);
        }
#pragma unroll
        for (int k = 0; k < 8; k++) {
            const float* asr = &As[cur][k][0];
            const float* bsr = &Bs[cur][k][0];
            float4 x0 = *(const float4*)(asr + ty*4);
            float4 x1 = *(const float4*)(asr + 64 + ty*4);
            float4 y0 = *(const float4*)(bsr + tx*4);
            float4 y1 = *(const float4*)(bsr + 64 + tx*4);
            float xa[8] = {x0.x,x0.y,x0.z,x0.w,x1.x,x1.y,x1.z,x1.w};
            float yb[8] = {y0.x,y0.y,y0.z,y0.w,y1.x,y1.y,y1.z,y1.w};
#pragma unroll
            for (int i = 0; i < 8; i++)
#pragma unroll
                for (int j = 0; j < 8; j++)
                    acc[i][j] += xa[i] * yb[j];
        }
        if (nx) {
            const int nxt = cur ^ 1;
            As[nxt][la_c+0][la_r] = a4n.x; As[nxt][la_c+1][la_r] = a4n.y;
            As[nxt][la_c+2][la_r] = a4n.z; As[nxt][la_c+3][la_r] = a4n.w;
            *(float4*)&Bs[nxt][lb_r][lb_c] = b4n;
            __syncthreads();
        }
    }

#pragma unroll
    for (int i = 0; i < 8; i++) {
        int r = m0 + ((i < 4) ? (ty*4 + i) : (64 + ty*4 + (i - 4)));
        float4 v0 = make_float4(acc[i][0], acc[i][1], acc[i][2], acc[i][3]);
        float4 v1 = make_float4(acc[i][4], acc[i][5], acc[i][6], acc[i][7]);
        *(float4*)(C + (size_t)r * N + n0 + tx*4)      = v0;
        *(float4*)(C + (size_t)r * N + n0 + 64 + tx*4) = v1;
    }
}

// ------------------------------ launcher ----------------------------------
extern "C" void kernel_launch(void* const* d_in, const int* in_sizes, int n_in,
                              void* d_out, int out_size) {
    const int*   enc_in  = (const int*)  d_in[0];
    const int*   dec_in  = (const int*)  d_in[1];
    const int*   enc_len = (const int*)  d_in[2];
    const int*   dec_len = (const int*)  d_in[3];
    const float* emb     = (const float*)d_in[4];
    const float* enc_k   = (const float*)d_in[5];
    const float* enc_b   = (const float*)d_in[6];
    const float* dec_k   = (const float*)d_in[7];
    const float* dec_b   = (const float*)d_in[8];
    const float* Wm      = (const float*)d_in[9];
    const float* Wq      = (const float*)d_in[10];
    const float* v_att   = (const float*)d_in[11];
    const float* attn_k  = (const float*)d_in[12];
    const float* out_k   = (const float*)d_in[13];
    float* out = (float*)d_out;

    // embeddings + zero h, c, attn
    k_init<<<2240, 256>>>(enc_in, dec_in, emb);

    // encoder recurrence
    for (int t = 0; t < T_; t++) {
        k_enc_gemm<<<dim3(16, KS_ENC), 256>>>(enc_k, t);
        k_enc_gates<<<64, 256>>>(enc_b, enc_len, t);
    }

    // keys = memory @ Wm   [1024,1024]@[1024,1024]
    sgemm128<<<dim3(8, 8), 256>>>(0, Wm, nullptr, 1024);

    // decoder recurrence with attention
    for (int t = 0; t < T_; t++) {
        k_dec_gemm<<<dim3(16, KS_DEC), 256>>>(dec_k, t);
        k_dec_gates<<<64, 256>>>(dec_b);
        k_query<<<dim3(8, KS_Q), 128>>>(Wq);
        k_scores<<<dim3(64, 16), 128>>>(v_att);
        k_ctx<<<dim3(8, 16), 128>>>(enc_len);
        k_attn2<<<dim3(8, KS_A), 128>>>(attn_k);
        k_attn_fin<<<64, 256>>>(dec_len, t);
    }

    // logits = dec_out @ out_kernel   [1024,1024]@[1024,32000]
    sgemm128<<<dim3(250, 8), 256>>>(1, out_k, out, 32000);
}